// round 3
// baseline (speedup 1.0000x reference)
#include <cuda_runtime.h>
#include <cstdint>

// Problem constants (fixed by the dataset)
#define NNODES 50000
#define EMAX   800000

// ---------------- device scratch (no allocations allowed) ----------------
__device__ int g_is32;                       // 1 if edge_index is int32, 0 if int64
__device__ int g_deg[NNODES];
__device__ int g_rowstart[NNODES + 1];
__device__ int g_cursor[NNODES];
__device__ int g_csr_src[EMAX];
__device__ __align__(128) float g_agg[(size_t)NNODES * 256];  // reused: layer1 uses 128 cols, layer2 256
__device__ __align__(128) float g_h[(size_t)NNODES * 256];    // hidden activations [N,256]

// ---------------- dtype detection ----------------
// If edge_index is int32, reading as u64 packs two indices per word; the high
// half is a random index in [0,50000) and is ~never zero for 64 consecutive
// words. int64 indices are < 2^32 always.
__global__ void detect_kernel(const void* eidx, long long n64) {
    const unsigned long long* p = (const unsigned long long*)eidx;
    int is32 = 0;
    long long lim = n64 < 64 ? n64 : 64;
    for (long long i = 0; i < lim; i++)
        if (p[i] > 0xFFFFFFFFULL) is32 = 1;
    g_is32 = is32;
}

__device__ __forceinline__ long long edge_val(const void* eidx, long long idx, int is32) {
    if (is32) return (long long)((const int*)eidx)[idx];
    return ((const long long*)eidx)[idx];
}

// ---------------- CSR build ----------------
__global__ void zero_build_kernel() {
    int i = blockIdx.x * blockDim.x + threadIdx.x;
    if (i < NNODES) { g_deg[i] = 0; g_cursor[i] = 0; }
}

__global__ void count_deg_kernel(const void* eidx, long long E) {
    long long e = (long long)blockIdx.x * blockDim.x + threadIdx.x;
    if (e >= E) return;
    int is32 = g_is32;
    int d = (int)edge_val(eidx, E + e, is32);   // dst row
    atomicAdd(&g_deg[d], 1);
}

// single-block exclusive scan of g_deg -> g_rowstart
__global__ void scan_kernel() {
    __shared__ int warp_sums[32];
    __shared__ int s_carry;
    int t = threadIdx.x;
    int lane = t & 31, wid = t >> 5;
    if (t == 0) s_carry = 0;
    __syncthreads();
    for (int base = 0; base < NNODES; base += 1024) {
        int i = base + t;
        int v = (i < NNODES) ? g_deg[i] : 0;
        int x = v;
        #pragma unroll
        for (int o = 1; o < 32; o <<= 1) {
            int y = __shfl_up_sync(0xFFFFFFFFu, x, o);
            if (lane >= o) x += y;
        }
        if (lane == 31) warp_sums[wid] = x;
        __syncthreads();
        if (wid == 0) {
            int s = warp_sums[lane];
            #pragma unroll
            for (int o = 1; o < 32; o <<= 1) {
                int y = __shfl_up_sync(0xFFFFFFFFu, s, o);
                if (lane >= o) s += y;
            }
            warp_sums[lane] = s;
        }
        __syncthreads();
        int block_excl = (wid > 0) ? warp_sums[wid - 1] : 0;
        int incl = x + block_excl;
        int carry = s_carry;
        if (i < NNODES) g_rowstart[i] = carry + incl - v;
        __syncthreads();
        if (t == 1023) s_carry = carry + incl;
        __syncthreads();
    }
    if (t == 0) g_rowstart[NNODES] = s_carry;
}

__global__ void scatter_kernel(const void* eidx, long long E) {
    long long e = (long long)blockIdx.x * blockDim.x + threadIdx.x;
    if (e >= E) return;
    int is32 = g_is32;
    int s = (int)edge_val(eidx, e, is32);       // src
    int d = (int)edge_val(eidx, E + e, is32);   // dst
    int pos = atomicAdd(&g_cursor[d], 1);
    g_csr_src[g_rowstart[d] + pos] = s;
}

// ---------------- mean aggregation: one warp per node ----------------
template <int C>  // feature width: 128 or 256
__global__ void agg_mean_kernel(const float* __restrict__ feat, float* __restrict__ out) {
    int node = blockIdx.x * (blockDim.x >> 5) + (threadIdx.x >> 5);
    if (node >= NNODES) return;
    int lane = threadIdx.x & 31;
    int start = g_rowstart[node];
    int end   = g_rowstart[node + 1];
    constexpr int V = C / 128;  // float4 chunks per lane
    float4 acc[V];
    #pragma unroll
    for (int v = 0; v < V; v++) acc[v] = make_float4(0.f, 0.f, 0.f, 0.f);
    for (int e = start; e < end; e++) {
        int s = g_csr_src[e];
        const float4* row = (const float4*)(feat + (size_t)s * C);
        #pragma unroll
        for (int v = 0; v < V; v++) {
            float4 r = row[lane + v * 32];
            acc[v].x += r.x; acc[v].y += r.y; acc[v].z += r.z; acc[v].w += r.w;
        }
    }
    int deg = end - start;
    float inv = (deg > 0) ? 1.0f / (float)deg : 0.0f;
    float4* o = (float4*)(out + (size_t)node * C);
    #pragma unroll
    for (int v = 0; v < V; v++) {
        acc[v].x *= inv; acc[v].y *= inv; acc[v].z *= inv; acc[v].w *= inv;
        o[lane + v * 32] = acc[v];
    }
}

// ---------------- dual-A SGEMM: out = A1@W1^T + A2@W2^T + b (opt ReLU) ----
// A1:[M,K1], A2:[M,K2], W1:[NO,K1], W2:[NO,K2] all row-major.
// 128x128 block tile, BK=16, 256 threads, 8x8 microtile.
__global__ void __launch_bounds__(256) gemm_dual_kernel(
    const float* __restrict__ A1, const float* __restrict__ A2,
    const float* __restrict__ W1, const float* __restrict__ W2,
    const float* __restrict__ bias, float* __restrict__ out,
    int M, int K1, int K2, int NO, int do_relu)
{
    __shared__ float As[16][128];
    __shared__ float Bs[16][128];

    int tid = threadIdx.x;
    int tx = tid & 15;       // column group
    int ty = tid >> 4;       // row group
    int blockN = blockIdx.x * 128;
    int blockM = blockIdx.y * 128;

    float acc[8][8];
    #pragma unroll
    for (int i = 0; i < 8; i++)
        #pragma unroll
        for (int j = 0; j < 8; j++) acc[i][j] = 0.f;

    int Ktot = K1 + K2;
    for (int k0 = 0; k0 < Ktot; k0 += 16) {
        const float* A; const float* W; int lda, kk0;
        if (k0 < K1) { A = A1; W = W1; lda = K1; kk0 = k0; }
        else         { A = A2; W = W2; lda = K2; kk0 = k0 - K1; }

        // cooperative load: 128 rows x 16 k each for A and W
        #pragma unroll
        for (int r = 0; r < 2; r++) {
            int idx = tid + r * 256;          // 0..511
            int m  = idx & 127;
            int k4 = idx >> 7;                // 0..3 -> 4 k's each
            int gm = blockM + m;
            float4 va = make_float4(0.f, 0.f, 0.f, 0.f);
            if (gm < M)
                va = *(const float4*)(A + (size_t)gm * lda + kk0 + k4 * 4);
            As[k4 * 4 + 0][m] = va.x;
            As[k4 * 4 + 1][m] = va.y;
            As[k4 * 4 + 2][m] = va.z;
            As[k4 * 4 + 3][m] = va.w;

            int gn = blockN + m;
            float4 vb = make_float4(0.f, 0.f, 0.f, 0.f);
            if (gn < NO)
                vb = *(const float4*)(W + (size_t)gn * lda + kk0 + k4 * 4);
            Bs[k4 * 4 + 0][m] = vb.x;
            Bs[k4 * 4 + 1][m] = vb.y;
            Bs[k4 * 4 + 2][m] = vb.z;
            Bs[k4 * 4 + 3][m] = vb.w;
        }
        __syncthreads();

        #pragma unroll
        for (int kk = 0; kk < 16; kk++) {
            float a[8], b[8];
            #pragma unroll
            for (int i = 0; i < 8; i++) a[i] = As[kk][ty * 8 + i];
            #pragma unroll
            for (int j = 0; j < 8; j++) b[j] = Bs[kk][tx * 8 + j];
            #pragma unroll
            for (int i = 0; i < 8; i++)
                #pragma unroll
                for (int j = 0; j < 8; j++)
                    acc[i][j] += a[i] * b[j];
        }
        __syncthreads();
    }

    // epilogue: bias (+ReLU), vectorized stores
    #pragma unroll
    for (int i = 0; i < 8; i++) {
        int gm = blockM + ty * 8 + i;
        if (gm >= M) continue;
        #pragma unroll
        for (int j0 = 0; j0 < 8; j0 += 4) {
            int gn = blockN + tx * 8 + j0;
            float4 c;
            c.x = acc[i][j0 + 0] + bias[gn + 0];
            c.y = acc[i][j0 + 1] + bias[gn + 1];
            c.z = acc[i][j0 + 2] + bias[gn + 2];
            c.w = acc[i][j0 + 3] + bias[gn + 3];
            if (do_relu) {
                c.x = fmaxf(c.x, 0.f); c.y = fmaxf(c.y, 0.f);
                c.z = fmaxf(c.z, 0.f); c.w = fmaxf(c.w, 0.f);
            }
            *(float4*)(out + (size_t)gm * NO + gn) = c;
        }
    }
}

// ---------------- launch ----------------
extern "C" void kernel_launch(void* const* d_in, const int* in_sizes, int n_in,
                              void* d_out, int out_size) {
    const float* x    = (const float*)d_in[0];
    const void*  eidx = d_in[1];
    const float* W1_l = (const float*)d_in[2];
    const float* b1   = (const float*)d_in[3];
    const float* W1_r = (const float*)d_in[4];
    const float* W2_l = (const float*)d_in[5];
    const float* b2   = (const float*)d_in[6];
    const float* W2_r = (const float*)d_in[7];
    float* out = (float*)d_out;

    long long E = (long long)in_sizes[1] / 2;   // element count / 2 regardless of dtype

    float* agg; float* h;
    cudaGetSymbolAddress((void**)&agg, g_agg);
    cudaGetSymbolAddress((void**)&h,   g_h);

    int eb = (int)((E + 255) / 256);
    int nb = (NNODES + 255) / 256;

    // 1. CSR build
    detect_kernel<<<1, 1>>>(eidx, E);           // E u64 words is safe in both layouts
    zero_build_kernel<<<nb, 256>>>();
    count_deg_kernel<<<eb, 256>>>(eidx, E);
    scan_kernel<<<1, 1024>>>();
    scatter_kernel<<<eb, 256>>>(eidx, E);

    // 2. layer 1: agg = mean(x[src]) ; h = relu(agg@W1_l^T + b1 + x@W1_r^T)
    int ab = (NNODES + 7) / 8;                  // 8 warps per block
    agg_mean_kernel<128><<<ab, 256>>>(x, agg);
    {
        dim3 grid(256 / 128, (NNODES + 127) / 128);
        gemm_dual_kernel<<<grid, 256>>>(agg, x, W1_l, W1_r, b1, h,
                                        NNODES, 128, 128, 256, 1);
    }

    // 3. layer 2: agg = mean(h[src]) ; out = agg@W2_l^T + b2 + h@W2_r^T
    agg_mean_kernel<256><<<ab, 256>>>(h, agg);
    {
        dim3 grid(128 / 128, (NNODES + 127) / 128);
        gemm_dual_kernel<<<grid, 256>>>(agg, h, W2_l, W2_r, b2, out,
                                        NNODES, 256, 256, 128, 0);
    }
}

// round 4
// speedup vs baseline: 2.8269x; 2.8269x over previous
#include <cuda_runtime.h>
#include <cstdint>

#define NNODES 50000
#define EMAX   800000

// ---------------- device scratch ----------------
__device__ int g_is32;
__device__ int g_deg[NNODES];
__device__ int g_rowstart[NNODES + 1];
__device__ int g_cursor[NNODES];
__device__ int g_part[64];
__device__ int g_csr_src[EMAX];
__device__ __align__(128) float g_cat[(size_t)NNODES * 256]; // layer1 A = [agg|x]; reused as P in layer2
__device__ __align__(128) float g_h[(size_t)NNODES * 256];   // hidden activations
__device__ __align__(128) float g_Bp1[256 * 256];            // packed tf32 weights layer1
__device__ __align__(128) float g_Bp2[256 * 256];            // packed tf32 weights layer2

__device__ __forceinline__ float to_tf32(float x) {
    float r;
    asm("cvt.rna.tf32.f32 %0, %1;" : "=f"(r) : "f"(x));
    return r;
}

// ---------------- dtype detection ----------------
__global__ void detect_kernel(const void* eidx, long long n64) {
    const unsigned long long* p = (const unsigned long long*)eidx;
    int is32 = 0;
    long long lim = n64 < 64 ? n64 : 64;
    for (long long i = 0; i < lim; i++)
        if (p[i] > 0xFFFFFFFFULL) is32 = 1;
    g_is32 = is32;
}

__device__ __forceinline__ long long edge_val(const void* eidx, long long idx, int is32) {
    if (is32) return (long long)((const int*)eidx)[idx];
    return ((const long long*)eidx)[idx];
}

// ---------------- CSR build ----------------
__global__ void zero_build_kernel() {
    int i = blockIdx.x * blockDim.x + threadIdx.x;
    if (i < NNODES) { g_deg[i] = 0; g_cursor[i] = 0; }
}

__global__ void count_deg_kernel(const void* eidx, long long E) {
    long long e = (long long)blockIdx.x * blockDim.x + threadIdx.x;
    if (e >= E) return;
    int is32 = g_is32;
    int d = (int)edge_val(eidx, E + e, is32);
    atomicAdd(&g_deg[d], 1);
}

// block-level exclusive scan (1024 elems/block) + per-block totals
__global__ void scan_block_kernel() {
    __shared__ int wsum[32];
    int blk = blockIdx.x, t = threadIdx.x;
    int i = blk * 1024 + t;
    int v = (i < NNODES) ? g_deg[i] : 0;
    int lane = t & 31, wid = t >> 5;
    int x = v;
    #pragma unroll
    for (int o = 1; o < 32; o <<= 1) {
        int y = __shfl_up_sync(0xFFFFFFFFu, x, o);
        if (lane >= o) x += y;
    }
    if (lane == 31) wsum[wid] = x;
    __syncthreads();
    if (wid == 0) {
        int s = wsum[lane];
        #pragma unroll
        for (int o = 1; o < 32; o <<= 1) {
            int y = __shfl_up_sync(0xFFFFFFFFu, s, o);
            if (lane >= o) s += y;
        }
        wsum[lane] = s;
    }
    __syncthreads();
    int excl = x - v + (wid ? wsum[wid - 1] : 0);
    if (i < NNODES) g_rowstart[i] = excl;
    if (t == 1023) g_part[blk] = excl + v;
}

__global__ void scan_tops_kernel(int nblk) {
    if (threadIdx.x == 0) {
        int run = 0;
        for (int b = 0; b < nblk; b++) { int v = g_part[b]; g_part[b] = run; run += v; }
        g_rowstart[NNODES] = run;
    }
}

__global__ void scan_add_kernel() {
    int i = blockIdx.x * 1024 + threadIdx.x;
    if (i < NNODES) g_rowstart[i] += g_part[blockIdx.x];
}

__global__ void scatter_kernel(const void* eidx, long long E) {
    long long e = (long long)blockIdx.x * blockDim.x + threadIdx.x;
    if (e >= E) return;
    int is32 = g_is32;
    int s = (int)edge_val(eidx, e, is32);
    int d = (int)edge_val(eidx, E + e, is32);
    int pos = atomicAdd(&g_cursor[d], 1);
    g_csr_src[g_rowstart[d] + pos] = s;
}

// ---------------- weight packing (tf32-converted) ----------------
// Bp1[n][k] : k<128 -> W1_l[n][k], else W1_r[n][k-128]        (n in [0,256))
__global__ void pack_b1_kernel(const float* __restrict__ Wl, const float* __restrict__ Wr) {
    int i = blockIdx.x * blockDim.x + threadIdx.x;   // 65536
    if (i >= 256 * 256) return;
    int n = i >> 8, k = i & 255;
    float v = (k < 128) ? Wl[n * 128 + k] : Wr[n * 128 + (k - 128)];
    g_Bp1[i] = to_tf32(v);
}
// Bp2[n][k] : n<128 -> W2_l[n][k], else W2_r[n-128][k]        (k in [0,256))
__global__ void pack_b2_kernel(const float* __restrict__ Wl, const float* __restrict__ Wr) {
    int i = blockIdx.x * blockDim.x + threadIdx.x;
    if (i >= 256 * 256) return;
    int n = i >> 8, k = i & 255;
    float v = (n < 128) ? Wl[n * 256 + k] : Wr[(n - 128) * 256 + k];
    g_Bp2[i] = to_tf32(v);
}

// ---------------- layer-1 aggregation fused with A concat ----------------
// cat[node][0:128]   = mean_{s in N(node)} x[s]
// cat[node][128:256] = x[node]
__global__ void agg_cat_kernel(const float* __restrict__ x, float* __restrict__ cat) {
    int node = blockIdx.x * (blockDim.x >> 5) + (threadIdx.x >> 5);
    if (node >= NNODES) return;
    int lane = threadIdx.x & 31;
    int start = g_rowstart[node], end = g_rowstart[node + 1];
    float4 acc = make_float4(0.f, 0.f, 0.f, 0.f);
    int e = start;
    for (; e + 1 < end; e += 2) {
        int s0 = g_csr_src[e], s1 = g_csr_src[e + 1];
        float4 r0 = ((const float4*)(x + (size_t)s0 * 128))[lane];
        float4 r1 = ((const float4*)(x + (size_t)s1 * 128))[lane];
        acc.x += r0.x + r1.x; acc.y += r0.y + r1.y;
        acc.z += r0.z + r1.z; acc.w += r0.w + r1.w;
    }
    if (e < end) {
        float4 r = ((const float4*)(x + (size_t)g_csr_src[e] * 128))[lane];
        acc.x += r.x; acc.y += r.y; acc.z += r.z; acc.w += r.w;
    }
    int deg = end - start;
    float inv = (deg > 0) ? 1.0f / (float)deg : 0.0f;
    acc.x *= inv; acc.y *= inv; acc.z *= inv; acc.w *= inv;
    float4* crow = (float4*)(cat + (size_t)node * 256);
    crow[lane] = acc;
    crow[32 + lane] = ((const float4*)(x + (size_t)node * 128))[lane];
}

// ---------------- tf32 tensor-core GEMM ----------------
// out[M,256] = A[M,256] @ B[256,256]^T  (+bias, +relu)
// block 128x128, k-tile 32, 8 warps (2x4), warp tile 64x32, mma m16n8k8.
__device__ __forceinline__ void mma_tf32(float c[4], uint32_t a0, uint32_t a1,
                                         uint32_t a2, uint32_t a3,
                                         uint32_t b0, uint32_t b1) {
    asm volatile(
        "mma.sync.aligned.m16n8k8.row.col.f32.tf32.tf32.f32 "
        "{%0,%1,%2,%3}, {%4,%5,%6,%7}, {%8,%9}, {%0,%1,%2,%3};"
        : "+f"(c[0]), "+f"(c[1]), "+f"(c[2]), "+f"(c[3])
        : "r"(a0), "r"(a1), "r"(a2), "r"(a3), "r"(b0), "r"(b1));
}

__global__ void __launch_bounds__(256) gemm_tf32_kernel(
    const float* __restrict__ A, const float* __restrict__ B,
    const float* __restrict__ bias, float* __restrict__ out,
    int M, int do_relu)
{
    __shared__ float As[128][36];
    __shared__ float Bs[128][36];

    int tid = threadIdx.x;
    int lane = tid & 31, warp = tid >> 5;
    int wm = (warp >> 2) * 64;     // warp m offset (0 or 64)
    int wn = (warp & 3) * 32;      // warp n offset
    int bM = blockIdx.y * 128;
    int bN = blockIdx.x * 128;
    int r = lane >> 2, cc = lane & 3;

    float c[4][4][4];
    #pragma unroll
    for (int mt = 0; mt < 4; mt++)
        #pragma unroll
        for (int nt = 0; nt < 4; nt++)
            #pragma unroll
            for (int q = 0; q < 4; q++) c[mt][nt][q] = 0.f;

    for (int kt = 0; kt < 8; kt++) {
        int k0 = kt * 32;
        #pragma unroll
        for (int i = 0; i < 4; i++) {
            int f = i * 256 + tid;           // 0..1023
            int m = f >> 3;
            int k4 = (f & 7) * 4;
            int gm = bM + m;
            float4 va = make_float4(0.f, 0.f, 0.f, 0.f);
            if (gm < M) va = *(const float4*)(A + (size_t)gm * 256 + k0 + k4);
            As[m][k4 + 0] = to_tf32(va.x);
            As[m][k4 + 1] = to_tf32(va.y);
            As[m][k4 + 2] = to_tf32(va.z);
            As[m][k4 + 3] = to_tf32(va.w);
            float4 vb = *(const float4*)(B + (size_t)(bN + m) * 256 + k0 + k4);
            *(float4*)&Bs[m][k4] = vb;       // already tf32
        }
        __syncthreads();

        #pragma unroll
        for (int ks = 0; ks < 4; ks++) {
            int kk = ks * 8;
            uint32_t a[4][4];
            #pragma unroll
            for (int mt = 0; mt < 4; mt++) {
                int mrow = wm + mt * 16;
                a[mt][0] = __float_as_uint(As[mrow + r][kk + cc]);
                a[mt][1] = __float_as_uint(As[mrow + r + 8][kk + cc]);
                a[mt][2] = __float_as_uint(As[mrow + r][kk + cc + 4]);
                a[mt][3] = __float_as_uint(As[mrow + r + 8][kk + cc + 4]);
            }
            uint32_t b[4][2];
            #pragma unroll
            for (int nt = 0; nt < 4; nt++) {
                int nrow = wn + nt * 8 + r;
                b[nt][0] = __float_as_uint(Bs[nrow][kk + cc]);
                b[nt][1] = __float_as_uint(Bs[nrow][kk + cc + 4]);
            }
            #pragma unroll
            for (int mt = 0; mt < 4; mt++)
                #pragma unroll
                for (int nt = 0; nt < 4; nt++)
                    mma_tf32(c[mt][nt], a[mt][0], a[mt][1], a[mt][2], a[mt][3],
                             b[nt][0], b[nt][1]);
        }
        __syncthreads();
    }

    // epilogue
    #pragma unroll
    for (int mt = 0; mt < 4; mt++) {
        int gm0 = bM + wm + mt * 16 + r;
        #pragma unroll
        for (int nt = 0; nt < 4; nt++) {
            int gn = bN + wn + nt * 8 + cc * 2;
            float bx = 0.f, by = 0.f;
            if (bias) { bx = bias[gn]; by = bias[gn + 1]; }
            float2 v0 = make_float2(c[mt][nt][0] + bx, c[mt][nt][1] + by);
            float2 v1 = make_float2(c[mt][nt][2] + bx, c[mt][nt][3] + by);
            if (do_relu) {
                v0.x = fmaxf(v0.x, 0.f); v0.y = fmaxf(v0.y, 0.f);
                v1.x = fmaxf(v1.x, 0.f); v1.y = fmaxf(v1.y, 0.f);
            }
            if (gm0 < M)     *(float2*)(out + (size_t)gm0 * 256 + gn) = v0;
            if (gm0 + 8 < M) *(float2*)(out + (size_t)(gm0 + 8) * 256 + gn) = v1;
        }
    }
}

// ---------------- layer-2 epilogue: out = mean_j P[j][:128] + P[i][128:] + b2 ----
__global__ void final_kernel(const float* __restrict__ P, const float* __restrict__ b2,
                             float* __restrict__ out) {
    int node = blockIdx.x * (blockDim.x >> 5) + (threadIdx.x >> 5);
    if (node >= NNODES) return;
    int lane = threadIdx.x & 31;
    int start = g_rowstart[node], end = g_rowstart[node + 1];
    float4 acc = make_float4(0.f, 0.f, 0.f, 0.f);
    int e = start;
    for (; e + 1 < end; e += 2) {
        int s0 = g_csr_src[e], s1 = g_csr_src[e + 1];
        float4 r0 = ((const float4*)(P + (size_t)s0 * 256))[lane];
        float4 r1 = ((const float4*)(P + (size_t)s1 * 256))[lane];
        acc.x += r0.x + r1.x; acc.y += r0.y + r1.y;
        acc.z += r0.z + r1.z; acc.w += r0.w + r1.w;
    }
    if (e < end) {
        float4 rr = ((const float4*)(P + (size_t)g_csr_src[e] * 256))[lane];
        acc.x += rr.x; acc.y += rr.y; acc.z += rr.z; acc.w += rr.w;
    }
    int deg = end - start;
    float inv = (deg > 0) ? 1.0f / (float)deg : 0.0f;
    float4 self = ((const float4*)(P + (size_t)node * 256))[32 + lane];
    float4 bb = ((const float4*)b2)[lane];
    float4 o;
    o.x = acc.x * inv + self.x + bb.x;
    o.y = acc.y * inv + self.y + bb.y;
    o.z = acc.z * inv + self.z + bb.z;
    o.w = acc.w * inv + self.w + bb.w;
    ((float4*)(out + (size_t)node * 128))[lane] = o;
}

// ---------------- launch ----------------
extern "C" void kernel_launch(void* const* d_in, const int* in_sizes, int n_in,
                              void* d_out, int out_size) {
    const float* x    = (const float*)d_in[0];
    const void*  eidx = d_in[1];
    const float* W1_l = (const float*)d_in[2];
    const float* b1   = (const float*)d_in[3];
    const float* W1_r = (const float*)d_in[4];
    const float* W2_l = (const float*)d_in[5];
    const float* b2   = (const float*)d_in[6];
    const float* W2_r = (const float*)d_in[7];
    float* out = (float*)d_out;

    long long E = (long long)in_sizes[1] / 2;

    float *cat, *h, *Bp1, *Bp2;
    cudaGetSymbolAddress((void**)&cat, g_cat);
    cudaGetSymbolAddress((void**)&h,   g_h);
    cudaGetSymbolAddress((void**)&Bp1, g_Bp1);
    cudaGetSymbolAddress((void**)&Bp2, g_Bp2);

    int eb = (int)((E + 255) / 256);
    int nb = (NNODES + 255) / 256;
    int sb = (NNODES + 1023) / 1024;     // 49

    // 1. CSR build
    detect_kernel<<<1, 1>>>(eidx, E);
    zero_build_kernel<<<nb, 256>>>();
    count_deg_kernel<<<eb, 256>>>(eidx, E);
    scan_block_kernel<<<sb, 1024>>>();
    scan_tops_kernel<<<1, 32>>>(sb);
    scan_add_kernel<<<sb, 1024>>>();
    scatter_kernel<<<eb, 256>>>(eidx, E);

    // 2. weight packing (tf32)
    pack_b1_kernel<<<256, 256>>>(W1_l, W1_r);
    pack_b2_kernel<<<256, 256>>>(W2_l, W2_r);

    // 3. layer 1
    int ab = (NNODES + 7) / 8;
    agg_cat_kernel<<<ab, 256>>>(x, cat);
    dim3 ggrid(2, (NNODES + 127) / 128);
    gemm_tf32_kernel<<<ggrid, 256>>>(cat, Bp1, b1, h, NNODES, 1);

    // 4. layer 2: P = h @ [W2_l;W2_r]^T (no bias), then aggregate+combine
    gemm_tf32_kernel<<<ggrid, 256>>>(h, Bp2, nullptr, cat, NNODES, 0);
    final_kernel<<<ab, 256>>>(cat, b2, out);
}

// round 8
// speedup vs baseline: 3.1044x; 1.0982x over previous
#include <cuda_runtime.h>
#include <cstdint>

#define NNODES 50000
#define EMAX   800000

// ---------------- device scratch ----------------
__device__ int g_is32;
__device__ int g_deg[NNODES];
__device__ int g_rowstart[NNODES + 1];
__device__ int g_cursor[NNODES];
__device__ int g_part[64];
__device__ int g_csr_src[EMAX];
__device__ __align__(128) float g_cat[(size_t)NNODES * 256]; // layer1 A = [agg|x] (tf32); reused as P
__device__ __align__(128) float g_h[(size_t)NNODES * 256];   // hidden activations (tf32-rounded)
__device__ __align__(128) float g_Bp1[256 * 256];            // packed tf32 weights layer1
__device__ __align__(128) float g_Bp2[256 * 256];            // packed tf32 weights layer2

__device__ __forceinline__ float to_tf32(float x) {
    float r;
    asm("cvt.rna.tf32.f32 %0, %1;" : "=f"(r) : "f"(x));
    return r;
}

__device__ __forceinline__ long long edge_val(const void* eidx, long long idx, int is32) {
    if (is32) return (long long)((const int*)eidx)[idx];
    return ((const long long*)eidx)[idx];
}

// ---------------- init: zero counters + dtype detect (merged) ----------------
__global__ void init_detect_kernel(const void* eidx) {
    int i = blockIdx.x * blockDim.x + threadIdx.x;
    if (i < NNODES) { g_deg[i] = 0; g_cursor[i] = 0; }
    if (blockIdx.x == 0 && threadIdx.x < 32) {
        const unsigned long long* p = (const unsigned long long*)eidx;
        bool big = false;
        #pragma unroll
        for (int j = 0; j < 2; j++)
            big |= p[threadIdx.x + j * 32] > 0xFFFFFFFFULL;
        unsigned bal = __ballot_sync(0xFFFFFFFFu, big);
        if (threadIdx.x == 0) g_is32 = bal ? 1 : 0;
    }
}

__global__ void count_deg_kernel(const void* eidx, long long E) {
    long long e = (long long)blockIdx.x * blockDim.x + threadIdx.x;
    if (e >= E) return;
    int is32 = g_is32;
    int d = (int)edge_val(eidx, E + e, is32);
    atomicAdd(&g_deg[d], 1);
}

// block-level exclusive scan (1024 elems/block) + per-block totals
__global__ void scan_block_kernel() {
    __shared__ int wsum[32];
    int blk = blockIdx.x, t = threadIdx.x;
    int i = blk * 1024 + t;
    int v = (i < NNODES) ? g_deg[i] : 0;
    int lane = t & 31, wid = t >> 5;
    int x = v;
    #pragma unroll
    for (int o = 1; o < 32; o <<= 1) {
        int y = __shfl_up_sync(0xFFFFFFFFu, x, o);
        if (lane >= o) x += y;
    }
    if (lane == 31) wsum[wid] = x;
    __syncthreads();
    if (wid == 0) {
        int s = wsum[lane];
        #pragma unroll
        for (int o = 1; o < 32; o <<= 1) {
            int y = __shfl_up_sync(0xFFFFFFFFu, s, o);
            if (lane >= o) s += y;
        }
        wsum[lane] = s;
    }
    __syncthreads();
    int excl = x - v + (wid ? wsum[wid - 1] : 0);
    if (i < NNODES) g_rowstart[i] = excl;
    if (t == 1023) g_part[blk] = excl + v;
}

// add block prefix (each block computes its own prefix of g_part; tops folded in)
__global__ void scan_add_kernel(int nblk) {
    __shared__ int s_off;
    int b = blockIdx.x;
    if (threadIdx.x == 0) {
        int run = 0;
        for (int j = 0; j < b; j++) run += g_part[j];
        s_off = run;
        if (b == nblk - 1) {
            int tot = run;
            for (int j = b; j < nblk; j++) tot += g_part[j];
            g_rowstart[NNODES] = tot;
        }
    }
    __syncthreads();
    int i = b * 1024 + threadIdx.x;
    if (i < NNODES) g_rowstart[i] += s_off;
}

__global__ void scatter_kernel(const void* eidx, long long E) {
    long long e = (long long)blockIdx.x * blockDim.x + threadIdx.x;
    if (e >= E) return;
    int is32 = g_is32;
    int s = (int)edge_val(eidx, e, is32);
    int d = (int)edge_val(eidx, E + e, is32);
    int pos = atomicAdd(&g_cursor[d], 1);
    g_csr_src[g_rowstart[d] + pos] = s;
}

// ---------------- weight packing (both layers, tf32-converted) ----------------
__global__ void pack_kernel(const float* __restrict__ W1l, const float* __restrict__ W1r,
                            const float* __restrict__ W2l, const float* __restrict__ W2r) {
    int i = blockIdx.x * blockDim.x + threadIdx.x;
    if (i < 65536) {
        int n = i >> 8, k = i & 255;
        float v = (k < 128) ? W1l[n * 128 + k] : W1r[n * 128 + (k - 128)];
        g_Bp1[i] = to_tf32(v);
    } else if (i < 131072) {
        int j = i - 65536;
        int n = j >> 8, k = j & 255;
        float v = (n < 128) ? W2l[n * 256 + k] : W2r[(n - 128) * 256 + k];
        g_Bp2[j] = to_tf32(v);
    }
}

// ---------------- layer-1 aggregation fused with A concat (tf32 outputs) -----
__global__ void agg_cat_kernel(const float* __restrict__ x, float* __restrict__ cat) {
    int node = blockIdx.x * (blockDim.x >> 5) + (threadIdx.x >> 5);
    if (node >= NNODES) return;
    int lane = threadIdx.x & 31;
    int start = g_rowstart[node], end = g_rowstart[node + 1];
    float4 acc = make_float4(0.f, 0.f, 0.f, 0.f);
    int e = start;
    for (; e + 3 < end; e += 4) {
        int s0 = g_csr_src[e], s1 = g_csr_src[e + 1];
        int s2 = g_csr_src[e + 2], s3 = g_csr_src[e + 3];
        float4 r0 = ((const float4*)(x + (size_t)s0 * 128))[lane];
        float4 r1 = ((const float4*)(x + (size_t)s1 * 128))[lane];
        float4 r2 = ((const float4*)(x + (size_t)s2 * 128))[lane];
        float4 r3 = ((const float4*)(x + (size_t)s3 * 128))[lane];
        acc.x += (r0.x + r1.x) + (r2.x + r3.x);
        acc.y += (r0.y + r1.y) + (r2.y + r3.y);
        acc.z += (r0.z + r1.z) + (r2.z + r3.z);
        acc.w += (r0.w + r1.w) + (r2.w + r3.w);
    }
    for (; e < end; e++) {
        float4 r = ((const float4*)(x + (size_t)g_csr_src[e] * 128))[lane];
        acc.x += r.x; acc.y += r.y; acc.z += r.z; acc.w += r.w;
    }
    int deg = end - start;
    float inv = (deg > 0) ? 1.0f / (float)deg : 0.0f;
    float4* crow = (float4*)(cat + (size_t)node * 256);
    crow[lane] = make_float4(to_tf32(acc.x * inv), to_tf32(acc.y * inv),
                             to_tf32(acc.z * inv), to_tf32(acc.w * inv));
    float4 xs = ((const float4*)(x + (size_t)node * 128))[lane];
    crow[32 + lane] = make_float4(to_tf32(xs.x), to_tf32(xs.y),
                                  to_tf32(xs.z), to_tf32(xs.w));
}

// ---------------- tf32 tensor-core GEMM, 2-stage cp.async pipeline ----------
// out[M,256] = A[M,256] @ B[256,256]^T  (mode=1: +bias,+relu,+tf32-round)
// A and B already tf32-rounded. block 128x128, BK=32, 8 warps 64x32 tiles.
#define SM_STRIDE 36
#define STAGE_FLOATS (128 * SM_STRIDE)
#define GEMM_SMEM_BYTES (4 * STAGE_FLOATS * 4)

__device__ __forceinline__ void mma_tf32(float c[4], uint32_t a0, uint32_t a1,
                                         uint32_t a2, uint32_t a3,
                                         uint32_t b0, uint32_t b1) {
    asm volatile(
        "mma.sync.aligned.m16n8k8.row.col.f32.tf32.tf32.f32 "
        "{%0,%1,%2,%3}, {%4,%5,%6,%7}, {%8,%9}, {%0,%1,%2,%3};"
        : "+f"(c[0]), "+f"(c[1]), "+f"(c[2]), "+f"(c[3])
        : "r"(a0), "r"(a1), "r"(a2), "r"(a3), "r"(b0), "r"(b1));
}

__global__ void __launch_bounds__(256, 2) gemm_tf32_kernel(
    const float* __restrict__ A, const float* __restrict__ B,
    const float* __restrict__ bias, float* __restrict__ out,
    int M, int mode)
{
    extern __shared__ float sm[];

    int tid = threadIdx.x;
    int lane = tid & 31, warp = tid >> 5;
    int wm = (warp >> 2) * 64;
    int wn = (warp & 3) * 32;
    int bM = blockIdx.y * 128;
    int bN = blockIdx.x * 128;
    int r = lane >> 2, cc = lane & 3;

    uint32_t sbase = (uint32_t)__cvta_generic_to_shared(sm);

    float c[4][4][4];
    #pragma unroll
    for (int mt = 0; mt < 4; mt++)
        #pragma unroll
        for (int nt = 0; nt < 4; nt++)
            #pragma unroll
            for (int q = 0; q < 4; q++) c[mt][nt][q] = 0.f;

    // async tile loader: A tile 128x32 + B tile 128x32, 8 cp.async/thread
    auto load_tile = [&](int kt, int s) {
        int k0 = kt * 32;
        #pragma unroll
        for (int i = 0; i < 4; i++) {
            int idx = i * 256 + tid;       // 0..1023
            int m = idx >> 3;              // 0..127
            int k4 = (idx & 7) * 4;        // 0..28
            const float* ga = A + (size_t)(bM + m) * 256 + k0 + k4;
            uint32_t da = sbase + (uint32_t)((s * STAGE_FLOATS + m * SM_STRIDE + k4) * 4);
            int sz = (bM + m < M) ? 16 : 0;
            asm volatile("cp.async.cg.shared.global [%0], [%1], 16, %2;"
                         :: "r"(da), "l"(ga), "r"(sz));
            const float* gb = B + (size_t)(bN + m) * 256 + k0 + k4;
            uint32_t db = sbase + (uint32_t)(((2 + s) * STAGE_FLOATS + m * SM_STRIDE + k4) * 4);
            asm volatile("cp.async.cg.shared.global [%0], [%1], 16, %2;"
                         :: "r"(db), "l"(gb), "r"(16));
        }
        asm volatile("cp.async.commit_group;");
    };

    load_tile(0, 0);

    for (int kt = 0; kt < 8; kt++) {
        if (kt + 1 < 8) {
            load_tile(kt + 1, (kt + 1) & 1);
            asm volatile("cp.async.wait_group 1;");
        } else {
            asm volatile("cp.async.wait_group 0;");
        }
        __syncthreads();

        const float* as = sm + (kt & 1) * STAGE_FLOATS;
        const float* bs = sm + (2 + (kt & 1)) * STAGE_FLOATS;

        #pragma unroll
        for (int ks = 0; ks < 4; ks++) {
            int kk = ks * 8;
            uint32_t a[4][4];
            #pragma unroll
            for (int mt = 0; mt < 4; mt++) {
                int mrow = wm + mt * 16;
                a[mt][0] = __float_as_uint(as[(mrow + r) * SM_STRIDE + kk + cc]);
                a[mt][1] = __float_as_uint(as[(mrow + r + 8) * SM_STRIDE + kk + cc]);
                a[mt][2] = __float_as_uint(as[(mrow + r) * SM_STRIDE + kk + cc + 4]);
                a[mt][3] = __float_as_uint(as[(mrow + r + 8) * SM_STRIDE + kk + cc + 4]);
            }
            uint32_t b[4][2];
            #pragma unroll
            for (int nt = 0; nt < 4; nt++) {
                int nrow = wn + nt * 8 + r;
                b[nt][0] = __float_as_uint(bs[nrow * SM_STRIDE + kk + cc]);
                b[nt][1] = __float_as_uint(bs[nrow * SM_STRIDE + kk + cc + 4]);
            }
            #pragma unroll
            for (int mt = 0; mt < 4; mt++)
                #pragma unroll
                for (int nt = 0; nt < 4; nt++)
                    mma_tf32(c[mt][nt], a[mt][0], a[mt][1], a[mt][2], a[mt][3],
                             b[nt][0], b[nt][1]);
        }
        __syncthreads();
    }

    // epilogue
    #pragma unroll
    for (int mt = 0; mt < 4; mt++) {
        int gm0 = bM + wm + mt * 16 + r;
        #pragma unroll
        for (int nt = 0; nt < 4; nt++) {
            int gn = bN + wn + nt * 8 + cc * 2;
            float bx = 0.f, by = 0.f;
            if (mode) { bx = bias[gn]; by = bias[gn + 1]; }
            float2 v0 = make_float2(c[mt][nt][0] + bx, c[mt][nt][1] + by);
            float2 v1 = make_float2(c[mt][nt][2] + bx, c[mt][nt][3] + by);
            if (mode) {
                v0.x = to_tf32(fmaxf(v0.x, 0.f)); v0.y = to_tf32(fmaxf(v0.y, 0.f));
                v1.x = to_tf32(fmaxf(v1.x, 0.f)); v1.y = to_tf32(fmaxf(v1.y, 0.f));
            }
            if (gm0 < M)     *(float2*)(out + (size_t)gm0 * 256 + gn) = v0;
            if (gm0 + 8 < M) *(float2*)(out + (size_t)(gm0 + 8) * 256 + gn) = v1;
        }
    }
}

// ---------------- layer-2 epilogue: out = mean_j P[j][:128] + P[i][128:] + b2 ----
__global__ void final_kernel(const float* __restrict__ P, const float* __restrict__ b2,
                             float* __restrict__ out) {
    int node = blockIdx.x * (blockDim.x >> 5) + (threadIdx.x >> 5);
    if (node >= NNODES) return;
    int lane = threadIdx.x & 31;
    int start = g_rowstart[node], end = g_rowstart[node + 1];
    float4 acc = make_float4(0.f, 0.f, 0.f, 0.f);
    int e = start;
    for (; e + 3 < end; e += 4) {
        int s0 = g_csr_src[e], s1 = g_csr_src[e + 1];
        int s2 = g_csr_src[e + 2], s3 = g_csr_src[e + 3];
        float4 r0 = ((const float4*)(P + (size_t)s0 * 256))[lane];
        float4 r1 = ((const float4*)(P + (size_t)s1 * 256))[lane];
        float4 r2 = ((const float4*)(P + (size_t)s2 * 256))[lane];
        float4 r3 = ((const float4*)(P + (size_t)s3 * 256))[lane];
        acc.x += (r0.x + r1.x) + (r2.x + r3.x);
        acc.y += (r0.y + r1.y) + (r2.y + r3.y);
        acc.z += (r0.z + r1.z) + (r2.z + r3.z);
        acc.w += (r0.w + r1.w) + (r2.w + r3.w);
    }
    for (; e < end; e++) {
        float4 rr = ((const float4*)(P + (size_t)g_csr_src[e] * 256))[lane];
        acc.x += rr.x; acc.y += rr.y; acc.z += rr.z; acc.w += rr.w;
    }
    int deg = end - start;
    float inv = (deg > 0) ? 1.0f / (float)deg : 0.0f;
    float4 self = ((const float4*)(P + (size_t)node * 256))[32 + lane];
    float4 bb = ((const float4*)b2)[lane];
    float4 o;
    o.x = acc.x * inv + self.x + bb.x;
    o.y = acc.y * inv + self.y + bb.y;
    o.z = acc.z * inv + self.z + bb.z;
    o.w = acc.w * inv + self.w + bb.w;
    ((float4*)(out + (size_t)node * 128))[lane] = o;
}

// ---------------- launch ----------------
extern "C" void kernel_launch(void* const* d_in, const int* in_sizes, int n_in,
                              void* d_out, int out_size) {
    const float* x    = (const float*)d_in[0];
    const void*  eidx = d_in[1];
    const float* W1_l = (const float*)d_in[2];
    const float* b1   = (const float*)d_in[3];
    const float* W1_r = (const float*)d_in[4];
    const float* W2_l = (const float*)d_in[5];
    const float* b2   = (const float*)d_in[6];
    const float* W2_r = (const float*)d_in[7];
    float* out = (float*)d_out;

    long long E = (long long)in_sizes[1] / 2;

    float *cat, *h, *Bp1, *Bp2;
    cudaGetSymbolAddress((void**)&cat, g_cat);
    cudaGetSymbolAddress((void**)&h,   g_h);
    cudaGetSymbolAddress((void**)&Bp1, g_Bp1);
    cudaGetSymbolAddress((void**)&Bp2, g_Bp2);

    cudaFuncSetAttribute(gemm_tf32_kernel,
                         cudaFuncAttributeMaxDynamicSharedMemorySize, GEMM_SMEM_BYTES);

    int eb = (int)((E + 255) / 256);
    int nb = (NNODES + 255) / 256;
    int sb = (NNODES + 1023) / 1024;     // 49

    // 1. CSR build
    init_detect_kernel<<<nb, 256>>>(eidx);
    count_deg_kernel<<<eb, 256>>>(eidx, E);
    scan_block_kernel<<<sb, 1024>>>();
    scan_add_kernel<<<sb, 1024>>>(sb);
    scatter_kernel<<<eb, 256>>>(eidx, E);

    // 2. weight packing (tf32)
    pack_kernel<<<512, 256>>>(W1_l, W1_r, W2_l, W2_r);

    // 3. layer 1
    int ab = (NNODES + 7) / 8;
    agg_cat_kernel<<<ab, 256>>>(x, cat);
    dim3 ggrid(2, (NNODES + 127) / 128);
    gemm_tf32_kernel<<<ggrid, 256, GEMM_SMEM_BYTES>>>(cat, Bp1, b1, h, NNODES, 1);

    // 4. layer 2: P = h @ [W2_l;W2_r]^T, then aggregate+combine
    gemm_tf32_kernel<<<ggrid, 256, GEMM_SMEM_BYTES>>>(h, Bp2, nullptr, cat, NNODES, 0);
    final_kernel<<<ab, 256>>>(cat, b2, out);
}